// round 16
// baseline (speedup 1.0000x reference)
#include <cuda_runtime.h>
#include <cuda_bf16.h>
#include <cstddef>

// ---------------------------------------------------------------------------
// ComplexGCN: 5x (GCNConv -> BN -> ReLU), last layer conv only.
// Strategy:
//   - Build CSR (dst-sorted adjacency) ONCE per launch (amortized over 5 layers):
//       deg histogram -> 3-kernel exclusive scan -> scatter (src idx + edge weight).
//   - Per layer: dense GEMM (W in smem, 4x4 register tile per thread), then a
//     dst-parallel gather-sum aggregation kernel with NO atomics, with the
//     conv-bias + BatchNorm + ReLU folded into its epilogue.
// ---------------------------------------------------------------------------

#define MAXN 100000
#define MAXE 1600000

__device__ float g_bufA[(size_t)MAXN * 128];
__device__ float g_bufB[(size_t)MAXN * 128];
__device__ int   g_deg[MAXN];          // in-degree counts (histogram)
__device__ float g_dinv[MAXN];         // rsqrt(deg+1)
__device__ float g_selfw[MAXN];        // 1/(deg+1)
__device__ int   g_rowptr[MAXN + 1];
__device__ int   g_fill[MAXN];
__device__ int   g_col[MAXE];          // src node per CSR slot
__device__ float g_w[MAXE];            // dinv[src]*dinv[dst] per CSR slot
__device__ int   g_blocksums[1024];
__device__ float g_scale[128];         // fused (BN) scale per column
__device__ float g_bias[128];          // fused (conv-bias + BN) bias per column

// ---------------------------- CSR construction ----------------------------

__global__ void deg_hist_kernel(const int* __restrict__ dst, int E) {
    int i = blockIdx.x * blockDim.x + threadIdx.x;
    if (i < E) atomicAdd(&g_deg[dst[i]], 1);
}

__global__ void deg_finish_kernel(int N) {
    int i = blockIdx.x * blockDim.x + threadIdx.x;
    if (i < N) {
        float d = (float)g_deg[i] + 1.0f;
        g_dinv[i]  = rsqrtf(d);
        g_selfw[i] = 1.0f / d;
    }
}

// Pass 1: per-block sums of g_deg
__global__ void scan1_kernel(int N) {
    __shared__ int sh[256];
    int t = threadIdx.x;
    int i = blockIdx.x * 256 + t;
    sh[t] = (i < N) ? g_deg[i] : 0;
    __syncthreads();
    for (int o = 128; o > 0; o >>= 1) {
        if (t < o) sh[t] += sh[t + o];
        __syncthreads();
    }
    if (t == 0) g_blocksums[blockIdx.x] = sh[0];
}

// Pass 2: exclusive scan of block sums (single block). Also sets rowptr[N]=E.
__global__ void scan2_kernel(int B, int N, int E) {
    __shared__ int sh[1024];
    int t = threadIdx.x;
    sh[t] = (t < B) ? g_blocksums[t] : 0;
    __syncthreads();
    for (int o = 1; o < 1024; o <<= 1) {
        int add = (t >= o) ? sh[t - o] : 0;
        __syncthreads();
        sh[t] += add;
        __syncthreads();
    }
    if (t < B) g_blocksums[t] = (t == 0) ? 0 : sh[t - 1];
    if (t == 0) g_rowptr[N] = E;
}

// Pass 3: in-block exclusive scan + block offset -> rowptr
__global__ void scan3_kernel(int N) {
    __shared__ int sh[256];
    int t = threadIdx.x;
    int i = blockIdx.x * 256 + t;
    int v = (i < N) ? g_deg[i] : 0;
    sh[t] = v;
    __syncthreads();
    for (int o = 1; o < 256; o <<= 1) {
        int add = (t >= o) ? sh[t - o] : 0;
        __syncthreads();
        sh[t] += add;
        __syncthreads();
    }
    if (i < N) g_rowptr[i] = g_blocksums[blockIdx.x] + sh[t] - v;
}

__global__ void scatter_kernel(const int* __restrict__ src,
                               const int* __restrict__ dst, int E) {
    int i = blockIdx.x * blockDim.x + threadIdx.x;
    if (i >= E) return;
    int d = dst[i];
    int s = src[i];
    int pos = g_rowptr[d] + atomicAdd(&g_fill[d], 1);
    g_col[pos] = s;
    g_w[pos]   = g_dinv[s] * g_dinv[d];
}

// --------------------------- BN parameter folding --------------------------
// scale = g * rsqrt(v+eps); bias = (b_conv - m)*scale + be.
// For the last layer (no BN): scale = 1, bias = b_conv.
__global__ void fuse_bn_kernel(const float* __restrict__ b,
                               const float* __restrict__ g,
                               const float* __restrict__ be,
                               const float* __restrict__ m,
                               const float* __restrict__ v,
                               int F) {
    int c = threadIdx.x;
    if (c >= F) return;
    if (g) {
        float s = g[c] * rsqrtf(v[c] + 1e-5f);
        g_scale[c] = s;
        g_bias[c]  = (b[c] - m[c]) * s + be[c];
    } else {
        g_scale[c] = 1.0f;
        g_bias[c]  = b[c];
    }
}

// --------------------------------- GEMM -----------------------------------
// Y[N,F_OUT] = X[N,F_IN] @ W[F_IN,F_OUT].  256 threads/block, W in smem as
// float4 columns-of-4, each thread computes ROWS_PT rows x 4 cols.
template <int F_IN, int F_OUT, int ROWS_PT>
__global__ void gemm_kernel(const float* __restrict__ X,
                            const float* __restrict__ W,
                            float* __restrict__ Y, int N) {
    constexpr int G   = F_OUT / 4;        // col groups of 4
    constexpr int RT  = 256 / G;          // row-threads per block
    constexpr int RPB = RT * ROWS_PT;     // rows per block
    constexpr int K4  = F_IN / 4;

    __shared__ float4 Wsh[F_IN * G];
    for (int i = threadIdx.x; i < F_IN * G; i += 256)
        Wsh[i] = reinterpret_cast<const float4*>(W)[i];
    __syncthreads();

    int cg   = threadIdx.x % G;
    int rt   = threadIdx.x / G;
    int row0 = blockIdx.x * RPB + rt * ROWS_PT;
    if (row0 >= N) return;

    const float4* X4 = reinterpret_cast<const float4*>(X);
    float4 acc[ROWS_PT] = {};

    if (row0 + ROWS_PT <= N) {
        for (int k = 0; k < K4; k++) {
            float4 w0 = Wsh[(4 * k + 0) * G + cg];
            float4 w1 = Wsh[(4 * k + 1) * G + cg];
            float4 w2 = Wsh[(4 * k + 2) * G + cg];
            float4 w3 = Wsh[(4 * k + 3) * G + cg];
#pragma unroll
            for (int r = 0; r < ROWS_PT; r++) {
                float4 x4 = X4[(size_t)(row0 + r) * K4 + k];
                acc[r].x += x4.x * w0.x + x4.y * w1.x + x4.z * w2.x + x4.w * w3.x;
                acc[r].y += x4.x * w0.y + x4.y * w1.y + x4.z * w2.y + x4.w * w3.y;
                acc[r].z += x4.x * w0.z + x4.y * w1.z + x4.z * w2.z + x4.w * w3.z;
                acc[r].w += x4.x * w0.w + x4.y * w1.w + x4.z * w2.w + x4.w * w3.w;
            }
        }
#pragma unroll
        for (int r = 0; r < ROWS_PT; r++)
            reinterpret_cast<float4*>(Y)[(size_t)(row0 + r) * G + cg] = acc[r];
    } else {
        int nr = N - row0;
        for (int k = 0; k < K4; k++) {
            float4 w0 = Wsh[(4 * k + 0) * G + cg];
            float4 w1 = Wsh[(4 * k + 1) * G + cg];
            float4 w2 = Wsh[(4 * k + 2) * G + cg];
            float4 w3 = Wsh[(4 * k + 3) * G + cg];
#pragma unroll
            for (int r = 0; r < ROWS_PT; r++) {
                if (r < nr) {
                    float4 x4 = X4[(size_t)(row0 + r) * K4 + k];
                    acc[r].x += x4.x * w0.x + x4.y * w1.x + x4.z * w2.x + x4.w * w3.x;
                    acc[r].y += x4.x * w0.y + x4.y * w1.y + x4.z * w2.y + x4.w * w3.y;
                    acc[r].z += x4.x * w0.z + x4.y * w1.z + x4.z * w2.z + x4.w * w3.z;
                    acc[r].w += x4.x * w0.w + x4.y * w1.w + x4.z * w2.w + x4.w * w3.w;
                }
            }
        }
        for (int r = 0; r < nr; r++)
            reinterpret_cast<float4*>(Y)[(size_t)(row0 + r) * G + cg] = acc[r];
    }
}

// ------------------------------ Aggregation --------------------------------
// One GS-thread group per dst node; lanes own columns. Gather-sum over CSR
// neighbors (no atomics), self-loop term as init, fused scale/bias(+ReLU)
// epilogue. Index/weight prefetch breaks the load dependence chain.
template <int F, bool RELU>
__global__ void agg_kernel(const float* __restrict__ XW,
                           float* __restrict__ OUT, int N) {
    constexpr int GS = (F < 32) ? F : 32;   // group size (threads per node)
    constexpr int V  = F / GS;              // columns per lane
    int gidx = (int)((blockIdx.x * (size_t)blockDim.x + threadIdx.x) / GS);
    int l    = threadIdx.x % GS;
    if (gidx >= N) return;
    int node = gidx;

    float acc[V];
    float sw = g_selfw[node];
    const float* xn = XW + (size_t)node * F;
#pragma unroll
    for (int v = 0; v < V; v++) acc[v] = xn[l + GS * v] * sw;

    int beg = g_rowptr[node];
    int end = g_rowptr[node + 1];
    int   nsrc = 0;
    float nw   = 0.f;
    if (beg < end) { nsrc = g_col[beg]; nw = g_w[beg]; }
    for (int i = beg; i < end; i++) {
        int   cs = nsrc;
        float cw = nw;
        if (i + 1 < end) { nsrc = g_col[i + 1]; nw = g_w[i + 1]; }
        const float* xr = XW + (size_t)cs * F;
#pragma unroll
        for (int v = 0; v < V; v++) acc[v] = fmaf(cw, xr[l + GS * v], acc[v]);
    }

#pragma unroll
    for (int v = 0; v < V; v++) {
        int c = l + GS * v;
        float val = fmaf(acc[v], g_scale[c], g_bias[c]);
        if (RELU) val = fmaxf(val, 0.0f);
        OUT[(size_t)node * F + c] = val;
    }
}

// -------------------------------- launch -----------------------------------

extern "C" void kernel_launch(void* const* d_in, const int* in_sizes, int n_in,
                              void* d_out, int out_size) {
    const float* x  = (const float*)d_in[0];
    const int*   ei = (const int*)d_in[1];
    const float* w1 = (const float*)d_in[2];  const float* b1 = (const float*)d_in[3];
    const float* w2 = (const float*)d_in[4];  const float* b2 = (const float*)d_in[5];
    const float* w3 = (const float*)d_in[6];  const float* b3 = (const float*)d_in[7];
    const float* w4 = (const float*)d_in[8];  const float* b4 = (const float*)d_in[9];
    const float* w5 = (const float*)d_in[10]; const float* b5 = (const float*)d_in[11];
    const float* g1 = (const float*)d_in[12]; const float* be1 = (const float*)d_in[13];
    const float* m1 = (const float*)d_in[14]; const float* v1 = (const float*)d_in[15];
    const float* g2 = (const float*)d_in[16]; const float* be2 = (const float*)d_in[17];
    const float* m2 = (const float*)d_in[18]; const float* v2 = (const float*)d_in[19];
    const float* g3 = (const float*)d_in[20]; const float* be3 = (const float*)d_in[21];
    const float* m3 = (const float*)d_in[22]; const float* v3 = (const float*)d_in[23];
    const float* g4 = (const float*)d_in[24]; const float* be4 = (const float*)d_in[25];
    const float* m4 = (const float*)d_in[26]; const float* v4 = (const float*)d_in[27];

    int N = in_sizes[0] / 128;
    int E = in_sizes[1] / 2;
    const int* src = ei;
    const int* dst = ei + E;

    void *pA = nullptr, *pB = nullptr, *pDeg = nullptr, *pFill = nullptr;
    cudaGetSymbolAddress(&pA, g_bufA);
    cudaGetSymbolAddress(&pB, g_bufB);
    cudaGetSymbolAddress(&pDeg, g_deg);
    cudaGetSymbolAddress(&pFill, g_fill);
    float* bufA = (float*)pA;
    float* bufB = (float*)pB;

    int B = (N + 255) / 256;

    // ---- CSR build (once per launch, reused by all 5 layers) ----
    cudaMemsetAsync(pDeg, 0, (size_t)N * sizeof(int));
    deg_hist_kernel<<<(E + 255) / 256, 256>>>(dst, E);
    deg_finish_kernel<<<B, 256>>>(N);
    scan1_kernel<<<B, 256>>>(N);
    scan2_kernel<<<1, 1024>>>(B, N, E);
    scan3_kernel<<<B, 256>>>(N);
    cudaMemsetAsync(pFill, 0, (size_t)N * sizeof(int));
    scatter_kernel<<<(E + 255) / 256, 256>>>(src, dst, E);

    // ---- Layer 1: 128 -> 64, BN+ReLU ----
    {
        constexpr int RPB = (256 / (64 / 4)) * 4;  // 64 rows/block
        gemm_kernel<128, 64, 4><<<(N + RPB - 1) / RPB, 256>>>(x, w1, bufA, N);
        fuse_bn_kernel<<<1, 128>>>(b1, g1, be1, m1, v1, 64);
        agg_kernel<64, true><<<((size_t)N * 32 + 255) / 256, 256>>>(bufA, bufB, N);
    }
    // ---- Layer 2: 64 -> 128, BN+ReLU ----
    {
        constexpr int RPB = (256 / (128 / 4)) * 4;  // 32 rows/block
        gemm_kernel<64, 128, 4><<<(N + RPB - 1) / RPB, 256>>>(bufB, w2, bufA, N);
        fuse_bn_kernel<<<1, 128>>>(b2, g2, be2, m2, v2, 128);
        agg_kernel<128, true><<<((size_t)N * 32 + 255) / 256, 256>>>(bufA, bufB, N);
    }
    // ---- Layer 3: 128 -> 64, BN+ReLU ----
    {
        constexpr int RPB = (256 / (64 / 4)) * 4;
        gemm_kernel<128, 64, 4><<<(N + RPB - 1) / RPB, 256>>>(bufB, w3, bufA, N);
        fuse_bn_kernel<<<1, 128>>>(b3, g3, be3, m3, v3, 64);
        agg_kernel<64, true><<<((size_t)N * 32 + 255) / 256, 256>>>(bufA, bufB, N);
    }
    // ---- Layer 4: 64 -> 32, BN+ReLU ----
    {
        constexpr int RPB = (256 / (32 / 4)) * 4;  // 128 rows/block
        gemm_kernel<64, 32, 4><<<(N + RPB - 1) / RPB, 256>>>(bufB, w4, bufA, N);
        fuse_bn_kernel<<<1, 128>>>(b4, g4, be4, m4, v4, 32);
        agg_kernel<32, true><<<((size_t)N * 32 + 255) / 256, 256>>>(bufA, bufB, N);
    }
    // ---- Layer 5: 32 -> 16, conv only, write d_out ----
    {
        constexpr int RPB = (256 / (16 / 4)) * 4;  // 256 rows/block
        gemm_kernel<32, 16, 4><<<(N + RPB - 1) / RPB, 256>>>(bufB, w5, bufA, N);
        fuse_bn_kernel<<<1, 128>>>(b5, nullptr, nullptr, nullptr, nullptr, 16);
        agg_kernel<16, false><<<((size_t)N * 16 + 255) / 256, 256>>>(bufA, (float*)d_out, N);
    }
}

// round 17
// speedup vs baseline: 1.1921x; 1.1921x over previous
#include <cuda_runtime.h>
#include <cuda_bf16.h>
#include <cstddef>

// ---------------------------------------------------------------------------
// ComplexGCN: 5x (GCNConv -> BN -> ReLU), last layer conv only.
//   - CSR built once per launch (histogram -> scan -> scatter), (col,w) packed
//     into one int2 per edge.
//   - Layer 2 (64->128) runs aggregate-first: Â(XW) == (ÂX)W, so we gather the
//     64-col input and fold BN+ReLU into the GEMM epilogue (saves 128-col gather).
//   - Aggregation: float4 gather lanes (GS=F/4), 2-edge unroll, dual
//     accumulators, no atomics, fused bias/BN/ReLU epilogue.
// ---------------------------------------------------------------------------

#define MAXN 100000
#define MAXE 1600000

__device__ float g_bufA[(size_t)MAXN * 128];
__device__ float g_bufB[(size_t)MAXN * 128];
__device__ int   g_deg[MAXN];
__device__ float g_dinv[MAXN];
__device__ float g_selfw[MAXN];
__device__ int   g_rowptr[MAXN + 1];
__device__ int   g_fill[MAXN];
__device__ int2  g_cw[MAXE];                 // (src, bits(weight)) per CSR slot
__device__ int   g_blocksums[1024];
__device__ __align__(16) float g_scale[128]; // fused BN scale per column
__device__ __align__(16) float g_bias[128];  // fused (conv-bias + BN) bias per column

// ---------------------------- CSR construction ----------------------------

__global__ void deg_hist_kernel(const int* __restrict__ dst, int E) {
    int i = blockIdx.x * blockDim.x + threadIdx.x;
    if (i < E) atomicAdd(&g_deg[dst[i]], 1);
}

__global__ void deg_finish_kernel(int N) {
    int i = blockIdx.x * blockDim.x + threadIdx.x;
    if (i < N) {
        float d = (float)g_deg[i] + 1.0f;
        g_dinv[i]  = rsqrtf(d);
        g_selfw[i] = 1.0f / d;
    }
}

__global__ void scan1_kernel(int N) {
    __shared__ int sh[256];
    int t = threadIdx.x;
    int i = blockIdx.x * 256 + t;
    sh[t] = (i < N) ? g_deg[i] : 0;
    __syncthreads();
    for (int o = 128; o > 0; o >>= 1) {
        if (t < o) sh[t] += sh[t + o];
        __syncthreads();
    }
    if (t == 0) g_blocksums[blockIdx.x] = sh[0];
}

__global__ void scan2_kernel(int B, int N, int E) {
    __shared__ int sh[1024];
    int t = threadIdx.x;
    sh[t] = (t < B) ? g_blocksums[t] : 0;
    __syncthreads();
    for (int o = 1; o < 1024; o <<= 1) {
        int add = (t >= o) ? sh[t - o] : 0;
        __syncthreads();
        sh[t] += add;
        __syncthreads();
    }
    if (t < B) g_blocksums[t] = (t == 0) ? 0 : sh[t - 1];
    if (t == 0) g_rowptr[N] = E;
}

__global__ void scan3_kernel(int N) {
    __shared__ int sh[256];
    int t = threadIdx.x;
    int i = blockIdx.x * 256 + t;
    int v = (i < N) ? g_deg[i] : 0;
    sh[t] = v;
    __syncthreads();
    for (int o = 1; o < 256; o <<= 1) {
        int add = (t >= o) ? sh[t - o] : 0;
        __syncthreads();
        sh[t] += add;
        __syncthreads();
    }
    if (i < N) g_rowptr[i] = g_blocksums[blockIdx.x] + sh[t] - v;
}

__global__ void scatter_kernel(const int* __restrict__ src,
                               const int* __restrict__ dst, int E) {
    int i = blockIdx.x * blockDim.x + threadIdx.x;
    if (i >= E) return;
    int d = dst[i];
    int s = src[i];
    int pos = g_rowptr[d] + atomicAdd(&g_fill[d], 1);
    g_cw[pos] = make_int2(s, __float_as_int(g_dinv[s] * g_dinv[d]));
}

// --------------------------- BN parameter folding --------------------------
__global__ void fuse_bn_kernel(const float* __restrict__ b,
                               const float* __restrict__ g,
                               const float* __restrict__ be,
                               const float* __restrict__ m,
                               const float* __restrict__ v,
                               int F) {
    int c = threadIdx.x;
    if (c >= F) return;
    if (g) {
        float s = g[c] * rsqrtf(v[c] + 1e-5f);
        g_scale[c] = s;
        g_bias[c]  = (b[c] - m[c]) * s + be[c];
    } else {
        g_scale[c] = 1.0f;
        g_bias[c]  = b[c];
    }
}

// --------------------------------- GEMM -----------------------------------
// Y[N,F_OUT] = X[N,F_IN] @ W[F_IN,F_OUT]. W in smem, 4-col x ROWS_PT register
// tile per thread. Optional fused scale/bias + ReLU epilogue (for the
// aggregate-first layer where BN follows the GEMM).
template <int F_IN, int F_OUT, int ROWS_PT, bool EPI>
__global__ void gemm_kernel(const float* __restrict__ X,
                            const float* __restrict__ W,
                            float* __restrict__ Y, int N) {
    constexpr int G   = F_OUT / 4;
    constexpr int RT  = 256 / G;
    constexpr int RPB = RT * ROWS_PT;
    constexpr int K4  = F_IN / 4;

    __shared__ float4 Wsh[F_IN * G];
    for (int i = threadIdx.x; i < F_IN * G; i += 256)
        Wsh[i] = reinterpret_cast<const float4*>(W)[i];
    __syncthreads();

    int cg   = threadIdx.x % G;
    int rt   = threadIdx.x / G;
    int row0 = blockIdx.x * RPB + rt * ROWS_PT;
    if (row0 >= N) return;

    float4 sc, bi;
    if (EPI) {
        sc = reinterpret_cast<const float4*>(g_scale)[cg];
        bi = reinterpret_cast<const float4*>(g_bias)[cg];
    }

    const float4* X4 = reinterpret_cast<const float4*>(X);
    float4 acc[ROWS_PT] = {};
    int nr = N - row0;
    if (nr > ROWS_PT) nr = ROWS_PT;

    if (nr == ROWS_PT) {
        for (int k = 0; k < K4; k++) {
            float4 w0 = Wsh[(4 * k + 0) * G + cg];
            float4 w1 = Wsh[(4 * k + 1) * G + cg];
            float4 w2 = Wsh[(4 * k + 2) * G + cg];
            float4 w3 = Wsh[(4 * k + 3) * G + cg];
#pragma unroll
            for (int r = 0; r < ROWS_PT; r++) {
                float4 x4 = X4[(size_t)(row0 + r) * K4 + k];
                acc[r].x += x4.x * w0.x + x4.y * w1.x + x4.z * w2.x + x4.w * w3.x;
                acc[r].y += x4.x * w0.y + x4.y * w1.y + x4.z * w2.y + x4.w * w3.y;
                acc[r].z += x4.x * w0.z + x4.y * w1.z + x4.z * w2.z + x4.w * w3.z;
                acc[r].w += x4.x * w0.w + x4.y * w1.w + x4.z * w2.w + x4.w * w3.w;
            }
        }
    } else {
        for (int k = 0; k < K4; k++) {
            float4 w0 = Wsh[(4 * k + 0) * G + cg];
            float4 w1 = Wsh[(4 * k + 1) * G + cg];
            float4 w2 = Wsh[(4 * k + 2) * G + cg];
            float4 w3 = Wsh[(4 * k + 3) * G + cg];
            for (int r = 0; r < nr; r++) {
                float4 x4 = X4[(size_t)(row0 + r) * K4 + k];
                acc[r].x += x4.x * w0.x + x4.y * w1.x + x4.z * w2.x + x4.w * w3.x;
                acc[r].y += x4.x * w0.y + x4.y * w1.y + x4.z * w2.y + x4.w * w3.y;
                acc[r].z += x4.x * w0.z + x4.y * w1.z + x4.z * w2.z + x4.w * w3.z;
                acc[r].w += x4.x * w0.w + x4.y * w1.w + x4.z * w2.w + x4.w * w3.w;
            }
        }
    }
    for (int r = 0; r < nr; r++) {
        float4 o = acc[r];
        if (EPI) {
            o.x = fmaxf(fmaf(o.x, sc.x, bi.x), 0.0f);
            o.y = fmaxf(fmaf(o.y, sc.y, bi.y), 0.0f);
            o.z = fmaxf(fmaf(o.z, sc.z, bi.z), 0.0f);
            o.w = fmaxf(fmaf(o.w, sc.w, bi.w), 0.0f);
        }
        reinterpret_cast<float4*>(Y)[(size_t)(row0 + r) * G + cg] = o;
    }
}

// ------------------------------ Aggregation --------------------------------
// GS = F/4 lanes per dst node, each lane owns one float4 column slab.
// 2-edge unrolled gather with dual accumulators; (col,w) packed int2 load.
// Optional fused scale/bias (+ReLU) epilogue.
template <int F, bool EPI, bool RELU>
__global__ void agg4_kernel(const float* __restrict__ XW,
                            float* __restrict__ OUT, int N) {
    constexpr int GS = F / 4;
    int gidx = (int)((blockIdx.x * (size_t)blockDim.x + threadIdx.x) / GS);
    int l    = threadIdx.x % GS;
    if (gidx >= N) return;

    const float4* X4 = reinterpret_cast<const float4*>(XW);
    float sw = g_selfw[gidx];
    float4 s = X4[(size_t)gidx * GS + l];
    float4 a0 = make_float4(s.x * sw, s.y * sw, s.z * sw, s.w * sw);
    float4 a1 = make_float4(0.f, 0.f, 0.f, 0.f);

    int i   = g_rowptr[gidx];
    int end = g_rowptr[gidx + 1];
    for (; i + 2 <= end; i += 2) {
        int2 cw0 = g_cw[i];
        int2 cw1 = g_cw[i + 1];
        float4 r0 = X4[(size_t)cw0.x * GS + l];
        float4 r1 = X4[(size_t)cw1.x * GS + l];
        float w0 = __int_as_float(cw0.y);
        float w1 = __int_as_float(cw1.y);
        a0.x = fmaf(w0, r0.x, a0.x); a0.y = fmaf(w0, r0.y, a0.y);
        a0.z = fmaf(w0, r0.z, a0.z); a0.w = fmaf(w0, r0.w, a0.w);
        a1.x = fmaf(w1, r1.x, a1.x); a1.y = fmaf(w1, r1.y, a1.y);
        a1.z = fmaf(w1, r1.z, a1.z); a1.w = fmaf(w1, r1.w, a1.w);
    }
    if (i < end) {
        int2 cw0 = g_cw[i];
        float4 r0 = X4[(size_t)cw0.x * GS + l];
        float w0 = __int_as_float(cw0.y);
        a0.x = fmaf(w0, r0.x, a0.x); a0.y = fmaf(w0, r0.y, a0.y);
        a0.z = fmaf(w0, r0.z, a0.z); a0.w = fmaf(w0, r0.w, a0.w);
    }
    a0.x += a1.x; a0.y += a1.y; a0.z += a1.z; a0.w += a1.w;

    if (EPI) {
        float4 sc = reinterpret_cast<const float4*>(g_scale)[l];
        float4 bi = reinterpret_cast<const float4*>(g_bias)[l];
        a0.x = fmaf(a0.x, sc.x, bi.x);
        a0.y = fmaf(a0.y, sc.y, bi.y);
        a0.z = fmaf(a0.z, sc.z, bi.z);
        a0.w = fmaf(a0.w, sc.w, bi.w);
        if (RELU) {
            a0.x = fmaxf(a0.x, 0.f); a0.y = fmaxf(a0.y, 0.f);
            a0.z = fmaxf(a0.z, 0.f); a0.w = fmaxf(a0.w, 0.f);
        }
    }
    reinterpret_cast<float4*>(OUT)[(size_t)gidx * GS + l] = a0;
}

// -------------------------------- launch -----------------------------------

extern "C" void kernel_launch(void* const* d_in, const int* in_sizes, int n_in,
                              void* d_out, int out_size) {
    const float* x  = (const float*)d_in[0];
    const int*   ei = (const int*)d_in[1];
    const float* w1 = (const float*)d_in[2];  const float* b1 = (const float*)d_in[3];
    const float* w2 = (const float*)d_in[4];  const float* b2 = (const float*)d_in[5];
    const float* w3 = (const float*)d_in[6];  const float* b3 = (const float*)d_in[7];
    const float* w4 = (const float*)d_in[8];  const float* b4 = (const float*)d_in[9];
    const float* w5 = (const float*)d_in[10]; const float* b5 = (const float*)d_in[11];
    const float* g1 = (const float*)d_in[12]; const float* be1 = (const float*)d_in[13];
    const float* m1 = (const float*)d_in[14]; const float* v1 = (const float*)d_in[15];
    const float* g2 = (const float*)d_in[16]; const float* be2 = (const float*)d_in[17];
    const float* m2 = (const float*)d_in[18]; const float* v2 = (const float*)d_in[19];
    const float* g3 = (const float*)d_in[20]; const float* be3 = (const float*)d_in[21];
    const float* m3 = (const float*)d_in[22]; const float* v3 = (const float*)d_in[23];
    const float* g4 = (const float*)d_in[24]; const float* be4 = (const float*)d_in[25];
    const float* m4 = (const float*)d_in[26]; const float* v4 = (const float*)d_in[27];

    int N = in_sizes[0] / 128;
    int E = in_sizes[1] / 2;
    const int* src = ei;
    const int* dst = ei + E;

    void *pA = nullptr, *pB = nullptr, *pDeg = nullptr, *pFill = nullptr;
    cudaGetSymbolAddress(&pA, g_bufA);
    cudaGetSymbolAddress(&pB, g_bufB);
    cudaGetSymbolAddress(&pDeg, g_deg);
    cudaGetSymbolAddress(&pFill, g_fill);
    float* bufA = (float*)pA;
    float* bufB = (float*)pB;

    int B = (N + 255) / 256;

    // ---- CSR build (once per launch) ----
    cudaMemsetAsync(pDeg, 0, (size_t)N * sizeof(int));
    deg_hist_kernel<<<(E + 255) / 256, 256>>>(dst, E);
    deg_finish_kernel<<<B, 256>>>(N);
    scan1_kernel<<<B, 256>>>(N);
    scan2_kernel<<<1, 1024>>>(B, N, E);
    scan3_kernel<<<B, 256>>>(N);
    cudaMemsetAsync(pFill, 0, (size_t)N * sizeof(int));
    scatter_kernel<<<(E + 255) / 256, 256>>>(src, dst, E);

    // ---- Layer 1: 128 -> 64, transform-first, BN+ReLU in agg epilogue ----
    {
        constexpr int RPB = (256 / (64 / 4)) * 4;
        fuse_bn_kernel<<<1, 128>>>(b1, g1, be1, m1, v1, 64);
        gemm_kernel<128, 64, 4, false><<<(N + RPB - 1) / RPB, 256>>>(x, w1, bufA, N);
        agg4_kernel<64, true, true><<<((size_t)N * 16 + 255) / 256, 256>>>(bufA, bufB, N);
    }
    // ---- Layer 2: 64 -> 128, AGGREGATE-FIRST, BN+ReLU in GEMM epilogue ----
    {
        constexpr int RPB = (256 / (128 / 4)) * 4;
        fuse_bn_kernel<<<1, 128>>>(b2, g2, be2, m2, v2, 128);
        agg4_kernel<64, false, false><<<((size_t)N * 16 + 255) / 256, 256>>>(bufB, bufA, N);
        gemm_kernel<64, 128, 4, true><<<(N + RPB - 1) / RPB, 256>>>(bufA, w2, bufB, N);
    }
    // ---- Layer 3: 128 -> 64, transform-first ----
    {
        constexpr int RPB = (256 / (64 / 4)) * 4;
        fuse_bn_kernel<<<1, 128>>>(b3, g3, be3, m3, v3, 64);
        gemm_kernel<128, 64, 4, false><<<(N + RPB - 1) / RPB, 256>>>(bufB, w3, bufA, N);
        agg4_kernel<64, true, true><<<((size_t)N * 16 + 255) / 256, 256>>>(bufA, bufB, N);
    }
    // ---- Layer 4: 64 -> 32, transform-first ----
    {
        constexpr int RPB = (256 / (32 / 4)) * 4;
        fuse_bn_kernel<<<1, 128>>>(b4, g4, be4, m4, v4, 32);
        gemm_kernel<64, 32, 4, false><<<(N + RPB - 1) / RPB, 256>>>(bufB, w4, bufA, N);
        agg4_kernel<32, true, true><<<((size_t)N * 8 + 255) / 256, 256>>>(bufA, bufB, N);
    }
    // ---- Layer 5: 32 -> 16, conv only -> d_out ----
    {
        constexpr int RPB = (256 / (16 / 4)) * 4;
        fuse_bn_kernel<<<1, 128>>>(b5, nullptr, nullptr, nullptr, nullptr, 16);
        gemm_kernel<32, 16, 4, false><<<(N + RPB - 1) / RPB, 256>>>(bufB, w5, bufA, N);
        agg4_kernel<16, true, false><<<((size_t)N * 4 + 255) / 256, 256>>>(bufA, (float*)d_out, N);
    }
}